// round 11
// baseline (speedup 1.0000x reference)
#include <cuda_runtime.h>

// MatrixMemory (R11 = final, R10 re-bench): direction-specialized CTAs.
//   write blocks (1 of 3, first in group): dM = d_out ⊗ key, 64 rows/block
//       (8 warps x 8 rows, 16 STG.128 per thread — long store bursts)
//   read blocks  (2 of 3): y = state @ query, 32 rows/block
//       (8 warps x 4 rows, 8 front-batched LDG.128 per thread)
// Lane-contiguous 16B accesses; .cs streaming hints; vectors via __ldg
// (1KB/batch, L2-resident). Session conclusion: pinned at the mixed
// read/write LTS/HBM ceiling (~6.8 TB/s ncu, 7.1 TB/s wall, 85.9% DRAM);
// traffic is compulsory (512MiB read + 512MiB write, zero reuse).

#define B_  2048
#define DK_ 256
#define DV_ 256

__global__ __launch_bounds__(256, 8)
void mm_split11_kernel(const float4* __restrict__ state,   // [B, DV, DK] as float4
                       const float4* __restrict__ query,   // [B, DK] as float4
                       const float4* __restrict__ keyv,    // [B, DK] as float4
                       const float*  __restrict__ dout,    // [B, DV]
                       float4*       __restrict__ y,       // [B, DV] as float4
                       float4*       __restrict__ dM)      // [B, DV, DK] as float4
{
    const int g = blockIdx.x / 3;
    const int r = blockIdx.x % 3;          // 0: write, 1: read, 2: read

    const int tid  = threadIdx.x;
    const int w    = tid >> 5;
    const int lane = tid & 31;

    if (r != 0) {
        // ---------------- READ stream: y = state @ query ----------------
        const int t  = g * 2 + (r - 1);        // 0..16383
        const int b  = t >> 3;                 // 8 tiles per batch
        const int rb = (t & 7) << 5;           // 32 rows per tile
        const long row0 = (long)b * DV_ + rb + w * 4;

        const float4* p = state + row0 * (DK_ / 4);

        float4 a[8];
        #pragma unroll
        for (int j = 0; j < 4; j++) {
            a[2*j]   = __ldcs(p + j * 64 + lane);
            a[2*j+1] = __ldcs(p + j * 64 + 32 + lane);
        }

        const float4 q0 = __ldg(query + b * 64 + lane);
        const float4 q1 = __ldg(query + b * 64 + 32 + lane);

        float yv[4];
        #pragma unroll
        for (int j = 0; j < 4; j++) {
            float s = a[2*j].x   * q0.x + a[2*j].y   * q0.y
                    + a[2*j].z   * q0.z + a[2*j].w   * q0.w
                    + a[2*j+1].x * q1.x + a[2*j+1].y * q1.y
                    + a[2*j+1].z * q1.z + a[2*j+1].w * q1.w;
            #pragma unroll
            for (int off = 16; off > 0; off >>= 1)
                s += __shfl_xor_sync(0xFFFFFFFFu, s, off);
            yv[j] = s;
        }
        if (lane == 0)
            y[row0 >> 2] = make_float4(yv[0], yv[1], yv[2], yv[3]);
    } else {
        // ---------------- WRITE stream: dM = d_out ⊗ key ----------------
        const int b  = g >> 2;                 // 4 tiles per batch
        const int rb = (g & 3) << 6;           // 64 rows per tile
        const long row0 = (long)b * DV_ + rb + w * 8;   // 8 rows per warp

        const float4 k0 = __ldg(keyv + b * 64 + lane);
        const float4 k1 = __ldg(keyv + b * 64 + 32 + lane);

        float dv[8];
        #pragma unroll
        for (int j = 0; j < 8; j++) dv[j] = __ldg(dout + row0 + j);

        float4* pd = dM + row0 * (DK_ / 4);
        #pragma unroll
        for (int j = 0; j < 8; j++) {
            const float d = dv[j];
            float4 o0 = make_float4(d * k0.x, d * k0.y, d * k0.z, d * k0.w);
            float4 o1 = make_float4(d * k1.x, d * k1.y, d * k1.z, d * k1.w);
            __stcs(pd + j * 64 + lane,      o0);
            __stcs(pd + j * 64 + 32 + lane, o1);
        }
    }
}

extern "C" void kernel_launch(void* const* d_in, const int* in_sizes, int n_in,
                              void* d_out, int out_size)
{
    const float4* state = (const float4*)d_in[0];
    const float4* query = (const float4*)d_in[1];
    const float4* keyv  = (const float4*)d_in[2];
    const float*  dov   = (const float*) d_in[3];

    float* out = (float*)d_out;
    float4* y  = (float4*)out;                     // [B, DV]
    float4* dM = (float4*)(out + (long)B_ * DV_);  // [B, DV, DK]

    // 8192 groups of 3 blocks: write tile (64 rows), then 2 read tiles (32 rows)
    dim3 grid(8192 * 3);
    dim3 block(256);
    mm_split11_kernel<<<grid, block>>>(state, query, keyv, dov, y, dM);
}

// round 12
// speedup vs baseline: 1.0053x; 1.0053x over previous
#include <cuda_runtime.h>

// MatrixMemory (final): fused single-pass, R1 configuration — the session's
// best harness draw (156.1us). y = state @ query (per-batch GEMV),
// dM = d_out ⊗ key (per-batch outer). Pure streaming: 512MiB read + 512MiB
// write, zero reuse -> compulsory traffic; measured ceiling ~7.1 TB/s wall
// (~89% of HBM spec) on a 50/50 mixed R/W stream.
//
// One warp per (b, v) row: 2 front-batched LDG.128 (.cs) + dot-reduce,
// 2 STG.128 (.cs) outer-product row write. q/k staged in smem per block.

#define B_  2048
#define DK_ 256
#define DV_ 256

__global__ __launch_bounds__(256, 8)
void mm_fused_kernel(const float4* __restrict__ state,   // [B, DV, DK] as float4
                     const float*  __restrict__ query,   // [B, DK]
                     const float*  __restrict__ keyv,    // [B, DK]
                     const float*  __restrict__ dout,    // [B, DV]
                     float*        __restrict__ y,       // [B, DV]
                     float4*       __restrict__ dM)      // [B, DV, DK] as float4
{
    const int b     = blockIdx.x >> 5;          // 32 blocks per batch
    const int vbase = (blockIdx.x & 31) << 3;   // 8 v-rows per block

    __shared__ float4 sq[64];   // query[b] as 64 float4
    __shared__ float4 sk[64];   // key[b]   as 64 float4

    const int tid = threadIdx.x;
    if (tid < 64) {
        sq[tid] = reinterpret_cast<const float4*>(query + (long)b * DK_)[tid];
    } else if (tid < 128) {
        sk[tid - 64] = reinterpret_cast<const float4*>(keyv + (long)b * DK_)[tid - 64];
    }
    __syncthreads();

    const int w    = tid >> 5;
    const int lane = tid & 31;
    const int v    = vbase + w;
    const long row = (long)b * DV_ + v;          // global row index (B*DV rows)

    // ---- read state row (1KB) with streaming hint, dot with q ----
    const float4* srow = state + row * (DK_ / 4);
    float4 a0 = __ldcs(srow + lane);             // k = lane*4 .. lane*4+3
    float4 a1 = __ldcs(srow + 32 + lane);        // k = 128 + lane*4 ..

    float4 q0 = sq[lane];
    float4 q1 = sq[lane + 32];

    float s = a0.x * q0.x + a0.y * q0.y + a0.z * q0.z + a0.w * q0.w
            + a1.x * q1.x + a1.y * q1.y + a1.z * q1.z + a1.w * q1.w;

    // warp reduce
    #pragma unroll
    for (int off = 16; off > 0; off >>= 1)
        s += __shfl_xor_sync(0xFFFFFFFFu, s, off);

    // ---- outer-product row write (1KB) with streaming hint ----
    const float dov = __ldg(dout + row);         // scalar, broadcast within warp

    float4 k0 = sk[lane];
    float4 k1 = sk[lane + 32];
    float4 o0 = make_float4(dov * k0.x, dov * k0.y, dov * k0.z, dov * k0.w);
    float4 o1 = make_float4(dov * k1.x, dov * k1.y, dov * k1.z, dov * k1.w);

    float4* drow = dM + row * (DK_ / 4);
    __stcs(drow + lane,      o0);
    __stcs(drow + lane + 32, o1);

    if (lane == 0) y[row] = s;
}

extern "C" void kernel_launch(void* const* d_in, const int* in_sizes, int n_in,
                              void* d_out, int out_size)
{
    const float4* state = (const float4*)d_in[0];
    const float*  query = (const float*) d_in[1];
    const float*  keyv  = (const float*) d_in[2];
    const float*  dov   = (const float*) d_in[3];

    float* out = (float*)d_out;
    float*  y  = out;                              // [B, DV]
    float4* dM = (float4*)(out + (long)B_ * DV_);  // [B, DV, DK]

    dim3 grid(B_ * 32);   // 32 blocks per batch, 8 warps each -> 8 rows/block
    dim3 block(256);
    mm_fused_kernel<<<grid, block>>>(state, query, keyv, dov, y, dM);
}

// round 13
// speedup vs baseline: 1.0117x; 1.0064x over previous
#include <cuda_runtime.h>

// MatrixMemory (final): fused single-pass, R1 configuration — the session's
// best harness draws (156.1/157.1us; beats the split family's 157.0-158.0
// under graph-replay conditions despite a slower isolated-ncu time).
// y = state @ query (per-batch GEMV), dM = d_out ⊗ key (per-batch outer).
// Pure streaming: 512MiB read + 512MiB write, zero reuse -> compulsory
// traffic; measured mixed-stream ceiling ~7.1 TB/s wall (~89% of HBM spec).
//
// One warp per (b, v) row: 2 front-batched LDG.128 (.cs) + dot-reduce,
// 2 STG.128 (.cs) outer-product row write. q/k staged in smem per block.

#define B_  2048
#define DK_ 256
#define DV_ 256

__global__ __launch_bounds__(256, 8)
void mm_fused_kernel(const float4* __restrict__ state,   // [B, DV, DK] as float4
                     const float*  __restrict__ query,   // [B, DK]
                     const float*  __restrict__ keyv,    // [B, DK]
                     const float*  __restrict__ dout,    // [B, DV]
                     float*        __restrict__ y,       // [B, DV]
                     float4*       __restrict__ dM)      // [B, DV, DK] as float4
{
    const int b     = blockIdx.x >> 5;          // 32 blocks per batch
    const int vbase = (blockIdx.x & 31) << 3;   // 8 v-rows per block

    __shared__ float4 sq[64];   // query[b] as 64 float4
    __shared__ float4 sk[64];   // key[b]   as 64 float4

    const int tid = threadIdx.x;
    if (tid < 64) {
        sq[tid] = reinterpret_cast<const float4*>(query + (long)b * DK_)[tid];
    } else if (tid < 128) {
        sk[tid - 64] = reinterpret_cast<const float4*>(keyv + (long)b * DK_)[tid - 64];
    }
    __syncthreads();

    const int w    = tid >> 5;
    const int lane = tid & 31;
    const int v    = vbase + w;
    const long row = (long)b * DV_ + v;          // global row index (B*DV rows)

    // ---- read state row (1KB) with streaming hint, dot with q ----
    const float4* srow = state + row * (DK_ / 4);
    float4 a0 = __ldcs(srow + lane);             // k = lane*4 .. lane*4+3
    float4 a1 = __ldcs(srow + 32 + lane);        // k = 128 + lane*4 ..

    float4 q0 = sq[lane];
    float4 q1 = sq[lane + 32];

    float s = a0.x * q0.x + a0.y * q0.y + a0.z * q0.z + a0.w * q0.w
            + a1.x * q1.x + a1.y * q1.y + a1.z * q1.z + a1.w * q1.w;

    // warp reduce
    #pragma unroll
    for (int off = 16; off > 0; off >>= 1)
        s += __shfl_xor_sync(0xFFFFFFFFu, s, off);

    // ---- outer-product row write (1KB) with streaming hint ----
    const float dov = __ldg(dout + row);         // scalar, broadcast within warp

    float4 k0 = sk[lane];
    float4 k1 = sk[lane + 32];
    float4 o0 = make_float4(dov * k0.x, dov * k0.y, dov * k0.z, dov * k0.w);
    float4 o1 = make_float4(dov * k1.x, dov * k1.y, dov * k1.z, dov * k1.w);

    float4* drow = dM + row * (DK_ / 4);
    __stcs(drow + lane,      o0);
    __stcs(drow + lane + 32, o1);

    if (lane == 0) y[row] = s;
}

extern "C" void kernel_launch(void* const* d_in, const int* in_sizes, int n_in,
                              void* d_out, int out_size)
{
    const float4* state = (const float4*)d_in[0];
    const float*  query = (const float*) d_in[1];
    const float*  keyv  = (const float*) d_in[2];
    const float*  dov   = (const float*) d_in[3];

    float* out = (float*)d_out;
    float*  y  = out;                              // [B, DV]
    float4* dM = (float4*)(out + (long)B_ * DV_);  // [B, DV, DK]

    dim3 grid(B_ * 32);   // 32 blocks per batch, 8 warps each -> 8 rows/block
    dim3 block(256);
    mm_fused_kernel<<<grid, block>>>(state, query, keyv, dov, y, dM);
}